// round 11
// baseline (speedup 1.0000x reference)
#include <cuda_runtime.h>
#include <cuda_fp16.h>

// TIME_WARPING: not-a-knot cubic spline fit + warped evaluation.
// IIR spline solve (lambda = sqrt(3)-2) fully register-resident with
// shuffle halos. Per-interval cubic coefficients PRE-BAKED to
// (y0, b, c, d) fp16x4 = 8 bytes in one shared uint2 array:
// eval = one LDS.64 + 2 cvt + 3 FMA.

#define S      4096
#define NT     256
#define CHUNK  16
#define W      6       // warm-up; |lambda|^6 ~ 3.7e-4

#define LAM     (-0.26794919243112270647f)
#define PL      ( 0.26794919243112270647f)
#define INV1ML2 ( 1.07735026918962576451f)

__device__ __forceinline__ int pswz(int i) { return i ^ ((i >> 4) & 15); }

// Pack interval i: s(t) = y0 + t*(b + t*(c + t*d)), coefficients from
// (y0, y1, M0, M1) computed in f32, rounded to fp16 at store.
__device__ __forceinline__ void pstore(uint2* spk, int i,
                                       float y0, float y1, float m0, float m1)
{
    float bb = (y1 - y0) - (2.f * m0 + m1) * (1.f / 6.f);
    float cc = 0.5f * m0;
    float dd = (m1 - m0) * (1.f / 6.f);
    __half2 h0 = __floats2half2_rn(y0, bb);
    __half2 h1 = __floats2half2_rn(cc, dd);
    uint2 v;
    v.x = *reinterpret_cast<unsigned*>(&h0);
    v.y = *reinterpret_cast<unsigned*>(&h1);
    spk[pswz(i)] = v;
}

// xa[m] = x[i0 - 7 + m], m in [0, 30).  y_{i0+k} = xa[7+k].
// MODE 0: interior. MODE 1: tid 0 (left not-a-knot images about node 1).
// MODE 2: tid NT-1 (right images about node S-2).
template<int MODE>
__device__ __forceinline__ void solve_and_pack(const float* xa, uint2* spk,
                                               int i0, float M1, float MS2)
{
    const float LP[6] = { 1.f, -0.26794919243112270647f, 0.07179676972449082073f,
                          -0.01923788646684063666f, 0.00515470534915383427f,
                          -0.00138119963856238452f };
    float pv[CHUNK];
    float p = 0.f, A = 0.f;

#define RR(m) (6.f * (xa[(m)] - 2.f * xa[(m) + 1] + xa[(m) + 2]))

    #pragma unroll
    for (int k = 0; k < CHUNK + 2 * W; ++k) {        // j = i0 - 6 + k
        float r;
        if (MODE == 1) {
            // j = k - 6
            if (k <= 5)       r = -RR(14 - k);        // j<0: -r(2-j)
            else if (k == 6)  r = -(RR(8) - M1);      // j=0: image of j=2
            else if (k == 7)  r = 0.f;                // j=1: Dirichlet
            else if (k == 8)  r = RR(8) - M1;         // j=2
            else              r = RR(k);
        } else if (MODE == 2) {
            // j = i0 - 6 + k, i0 = S-16
            if (k == 19)      r = RR(19) - MS2;       // j = S-3
            else if (k == 20) r = 0.f;                // j = S-2
            else if (k == 21) r = -(RR(19) - MS2);    // j = S-1 mirrors S-3
            else if (k >= 22) r = -RR(46 - k);        // j>S-1: -r(2(S-2)-j)
            else              r = RR(k);
        } else {
            r = RR(k);
        }
        if (k < CHUNK + W) {
            p = fmaf(LAM, p, r);
            if (k >= W) pv[k - W] = p;
        } else {
            A = fmaf(LP[k - (CHUNK + W)], r, A);
        }
    }
#undef RR

    // Backward pass fused with coefficient baking. q_16 seeded analytically.
    float q      = fmaf(LAM, pv[CHUNK - 1], A) * INV1ML2;
    float u_next = PL * q;                   // M_{i0+16} (unused in MODE 2)
    float u2     = 0.f;

    #pragma unroll
    for (int k = CHUNK - 1; k >= 0; --k) {
        q = fmaf(LAM, q, pv[k]);
        float u = PL * q;                    // M_{i0+k}

        if (MODE == 1) {
            if (k == 2) u2 = u;
            if (k == 1) u = M1;              // exact M1
            if (k == 0) u = 2.f * M1 - u2;   // M0 = 2*M1 - M2
        }
        if (MODE == 2) {
            if (k == 15) { u_next = 0.f; continue; }   // interval S-1 unused
            if (k == 14) { u_next = MS2; continue; }   // store deferred
            if (k == 13) {
                // interval S-2 = i0+14: (y_{S-2}, y_{S-1}, MS2, M_{S-1})
                pstore(spk, i0 + 14, xa[21], xa[22], MS2, 2.f * MS2 - u);
                // fall through: generic store of interval i0+13
            }
        }

        pstore(spk, i0 + k, xa[7 + k], xa[8 + k], u, u_next);
        u_next = u;
    }
}

__global__ __launch_bounds__(NT)
void tw_kernel(const float* __restrict__ x,
               const float* __restrict__ scale,
               const int* __restrict__ mask,
               float* __restrict__ out, int C)
{
    __shared__ uint2 spk[S];    // packed (y0, b, c, d) fp16x4 per interval

    const int c    = blockIdx.x;
    const int b    = blockIdx.y;
    const int tid  = threadIdx.x;
    const int lane = tid & 31;
    const size_t row = ((size_t)b * C + c) * (size_t)S;
    const float* xr   = x + row;
    float*       orow = out + row;

    if (mask[b] == 0) {                      // uniform per block
        const float4* xi = (const float4*)xr;
        float4*       oo = (float4*)orow;
        #pragma unroll
        for (int g = 0; g < S / 4 / NT; ++g)
            oo[g * NT + tid] = xi[g * NT + tid];
        return;
    }

    const float scl = scale[b];
    const int   i0  = tid * CHUNK;

    // Own chunk: 4x LDG.128 -> xa[7..22]
    float xa[30];
    {
        const float4* xv = (const float4*)(xr + i0);
        float4 a0 = xv[0], a1 = xv[1], a2 = xv[2], a3 = xv[3];
        xa[7]  = a0.x; xa[8]  = a0.y; xa[9]  = a0.z; xa[10] = a0.w;
        xa[11] = a1.x; xa[12] = a1.y; xa[13] = a1.z; xa[14] = a1.w;
        xa[15] = a2.x; xa[16] = a2.y; xa[17] = a2.z; xa[18] = a2.w;
        xa[19] = a3.x; xa[20] = a3.y; xa[21] = a3.z; xa[22] = a3.w;
    }

    // Halos via warp shuffle; warp-edge lanes patch from global.
    #pragma unroll
    for (int q = 0; q < 7; ++q)
        xa[q] = __shfl_up_sync(0xffffffffu, xa[16 + q], 1);
    #pragma unroll
    for (int q = 0; q < 7; ++q)
        xa[23 + q] = __shfl_down_sync(0xffffffffu, xa[7 + q], 1);
    if (lane == 0 && tid != 0) {
        #pragma unroll
        for (int q = 0; q < 7; ++q) xa[q] = xr[i0 - 7 + q];
    }
    if (lane == 31 && tid != NT - 1) {
        #pragma unroll
        for (int q = 0; q < 7; ++q) xa[23 + q] = xr[i0 + 16 + q];
    }

    const float M1  = xa[7]  - 2.f * xa[8]  + xa[9];    // tid 0:   x0-2x1+x2
    const float MS2 = xa[20] - 2.f * xa[21] + xa[22];   // tid NT-1: M_{S-2}

    if (tid == 0)            solve_and_pack<1>(xa, spk, i0, M1, MS2);
    else if (tid == NT - 1)  solve_and_pack<2>(xa, spk, i0, M1, MS2);
    else                     solve_and_pack<0>(xa, spk, i0, M1, MS2);

    __syncthreads();

    // Warped cubic evaluation, stride-1 lane mapping; one LDS.64, 3 FMA.
    #pragma unroll
    for (int g = 0; g < S / NT; ++g) {
        const int v = g * NT + tid;
        float wv = fminf((float)v * scl, (float)(S - 1));
        int idx = (int)wv;
        if (idx > S - 2) idx = S - 2;
        float tt = wv - (float)idx;

        uint2 pk = spk[pswz(idx)];
        __half2 h0 = *reinterpret_cast<__half2*>(&pk.x);   // (y0, b)
        __half2 h1 = *reinterpret_cast<__half2*>(&pk.y);   // (c,  d)
        float2 f0 = __half22float2(h0);
        float2 f1 = __half22float2(h1);

        orow[v] = fmaf(tt, fmaf(tt, fmaf(tt, f1.y, f1.x), f0.y), f0.x);
    }
}

extern "C" void kernel_launch(void* const* d_in, const int* in_sizes, int n_in,
                              void* d_out, int out_size)
{
    const float* x     = (const float*)d_in[0];
    const float* scale = (const float*)d_in[1];
    const int*   mask  = (const int*)d_in[2];
    float*       out   = (float*)d_out;

    const int B = in_sizes[1];
    const int C = in_sizes[0] / (B * S);

    dim3 grid(C, B);
    tw_kernel<<<grid, NT>>>(x, scale, mask, out, C);
}